// round 17
// baseline (speedup 1.0000x reference)
#include <cuda_runtime.h>
#include <math.h>

#define B_DIM 64
#define C_DIM 80
#define T_DIM 16384
#define NTHREADS 256
#define NWARPS 8
#define NBINR 896            // real bins covering [-0.875, 0.875) at 1/512
#define NBINP 1024           // padded for scan
#define CAP 1024
#define BINBUF 64
#define FULL 0xFFFFFFFFu

// order-preserving float <-> u32 key (exact total order incl. ties/-0)
__device__ __forceinline__ unsigned f2k(float f) {
    unsigned u = __float_as_uint(f);
    return u ^ ((unsigned)((int)u >> 31) | 0x80000000u);
}
__device__ __forceinline__ float k2f(unsigned k) {
    unsigned m = (k & 0x80000000u) ? 0x80000000u : 0xFFFFFFFFu;
    return __uint_as_float(k ^ m);
}

// restricted bin coordinate: bf = f*512 + 448  (exact sign; Sterbenz near 0)
// bin b covers [ (b-448)/512, (b-447)/512 ) -- edges exactly representable
__device__ __forceinline__ float binf(float f) { return fmaf(f, 512.0f, 448.0f); }
__device__ __forceinline__ float binlo_val(int b2) {
    return (float)(b2 - 448) * 0.001953125f;   // /512, exact
}

__global__ void __launch_bounds__(NTHREADS, 8)
statpool_kernel(const float* __restrict__ x, const int* __restrict__ lengths,
                float* __restrict__ out) {
    extern __shared__ unsigned sh[];
    unsigned* hist = sh;                 // [1024] counts -> inclusive cumsum
    float* list = (float*)(sh + NBINP);  // [CAP] window candidates

    __shared__ float red_s[NWARPS], red_s2[NWARPS];
    __shared__ unsigned wtot[NWARPS], wbase[NWARPS];
    __shared__ int s_k[6];
    __shared__ float s_w[3];
    __shared__ int s_clow;
    __shared__ int s_bin[6], s_krem[6], s_m[6];
    __shared__ float s_wl[3], s_wh[3];
    __shared__ int s_cnt;
    __shared__ int bcnt[6];
    __shared__ unsigned binbuf[6 * BINBUF];
    __shared__ unsigned s_keyout[6];

    const int row = blockIdx.x;
    const int b = row / C_DIM, c = row % C_DIM;
    const int n = lengths[b];
    const int tid = threadIdx.x, lane = tid & 31, warp = tid >> 5;

    for (int i = tid; i < NBINP; i += NTHREADS) hist[i] = 0u;
    if (tid < 6) bcnt[tid] = 0;
    if (tid == 0) { s_cnt = 0; s_clow = 0; }
    __syncthreads();

    // ---- pass 1: sums + restricted histogram + below-range register count ----
    const float* xrow = x + (size_t)row * T_DIM;
    const float4* x4 = (const float4*)xrow;
    const int nfull = n >> 2;
    float sum = 0.f, sumsq = 0.f;
    int clow = 0;
    for (int i = tid; i < nfull; i += NTHREADS) {
        float4 v = x4[i];
        sum += v.x + v.y + v.z + v.w;
        sumsq = fmaf(v.x, v.x, sumsq); sumsq = fmaf(v.y, v.y, sumsq);
        sumsq = fmaf(v.z, v.z, sumsq); sumsq = fmaf(v.w, v.w, sumsq);
        float b0 = binf(v.x), b1 = binf(v.y), b2 = binf(v.z), b3 = binf(v.w);
        clow += (b0 < 0.f) + (b1 < 0.f) + (b2 < 0.f) + (b3 < 0.f);
        if (b0 >= 0.f && b0 < 896.f) atomicAdd(&hist[(int)b0], 1u);
        if (b1 >= 0.f && b1 < 896.f) atomicAdd(&hist[(int)b1], 1u);
        if (b2 >= 0.f && b2 < 896.f) atomicAdd(&hist[(int)b2], 1u);
        if (b3 >= 0.f && b3 < 896.f) atomicAdd(&hist[(int)b3], 1u);
    }
    if (tid == 0) {                      // tail: <=3 elements
        for (int t = nfull << 2; t < n; ++t) {
            float f = xrow[t];
            sum += f; sumsq = fmaf(f, f, sumsq);
            float bf = binf(f);
            clow += (bf < 0.f);
            if (bf >= 0.f && bf < 896.f) atomicAdd(&hist[(int)bf], 1u);
        }
    }
#pragma unroll
    for (int o = 16; o; o >>= 1) {
        sum += __shfl_down_sync(FULL, sum, o);
        sumsq += __shfl_down_sync(FULL, sumsq, o);
        clow += __shfl_down_sync(FULL, clow, o);
    }
    if (lane == 0) {
        red_s[warp] = sum; red_s2[warp] = sumsq;
        atomicAdd(&s_clow, clow);
    }
    __syncthreads();

    // ---- inclusive scan of hist (4 bins/thread over 1024 padded) ----
    unsigned vb[4], loc = 0;
#pragma unroll
    for (int d = 0; d < 4; ++d) { vb[d] = hist[tid * 4 + d]; loc += vb[d]; }
    unsigned inc = loc;
#pragma unroll
    for (int o = 1; o < 32; o <<= 1) {
        unsigned t = __shfl_up_sync(FULL, inc, o);
        if (lane >= o) inc += t;
    }
    if (lane == 31) wtot[warp] = inc;
    __syncthreads();

    if (warp == 0) {
        unsigned t = (lane < NWARPS) ? wtot[lane] : 0u;
        unsigned ti = t;
#pragma unroll
        for (int o = 1; o < NWARPS; o <<= 1) {
            unsigned u = __shfl_up_sync(FULL, ti, o);
            if (lane >= o) ti += u;
        }
        if (lane < NWARPS) wbase[lane] = ti - t;
    } else if (tid == 32) {
        // mean/std + rank targets (concurrent with warp 0's base scan)
        float s = 0.f, s2 = 0.f;
#pragma unroll
        for (int w = 0; w < NWARPS; ++w) { s += red_s[w]; s2 += red_s2[w]; }
        float fn = (float)n;
        float mean = s / fn;
        float var = fmaxf(s2 / fn - mean * mean, 1e-6f);
        out[b * (5 * C_DIM) + 0 * C_DIM + c] = mean;
        out[b * (5 * C_DIM) + 1 * C_DIM + c] = sqrtf(var);
        float n1 = (float)(n - 1);
        const float qs[3] = {0.25f, 0.5f, 0.75f};
#pragma unroll
        for (int q = 0; q < 3; ++q) {
            float pos = qs[q] * n1;
            float flo = floorf(pos);
            s_k[2 * q]     = (int)flo;
            s_k[2 * q + 1] = (int)ceilf(pos);
            s_w[q] = pos - flo;
        }
    }
    __syncthreads();

    unsigned run = wbase[warp] + (inc - loc);
#pragma unroll
    for (int d = 0; d < 4; ++d) { run += vb[d]; hist[tid * 4 + d] = run; }
    __syncthreads();

    // ---- locate target bins (rank within restricted range = k - clow) ----
    if (tid < 6) {
        int kr = s_k[tid] - s_clow;
        int lo = 0, hi = NBINR - 1;
        if (kr >= 0) {
            while (lo < hi) {
                int mid = (lo + hi) >> 1;
                if ((int)hist[mid] > kr) hi = mid; else lo = mid + 1;
            }
        }
        int below = lo ? (int)hist[lo - 1] : 0;
        s_bin[tid] = lo;
        s_krem[tid] = kr - below;        // negative if kr<0 -> gate fails
        s_m[tid] = (int)hist[lo] - below;
    }
    __syncthreads();

    // ---- derived narrow windows (bin-aligned, widened +-1 bin) ----
    if (tid == 0) {
#pragma unroll
        for (int q = 0; q < 3; ++q) {
            int blo = min(s_bin[2 * q], s_bin[2 * q + 1]) - 1;
            int bhi = max(s_bin[2 * q], s_bin[2 * q + 1]) + 2;
            blo = max(blo, 0); bhi = min(bhi, NBINR);
            s_wl[q] = binlo_val(blo);
            s_wh[q] = binlo_val(bhi);
        }
    }
    __syncthreads();

    const float wl0 = s_wl[0], wh0 = s_wh[0];
    const float wl1 = s_wl[1], wh1 = s_wh[1];
    const float wl2 = s_wl[2], wh2 = s_wh[2];

    // ---- pass 2: window candidacy only (L2-hot LDG + fma-pipe compares) ----
    for (int i = tid; i < nfull; i += NTHREADS) {
        float4 v = x4[i];
        float vv[4] = {v.x, v.y, v.z, v.w};
#pragma unroll
        for (int j = 0; j < 4; ++j) {
            float f = vv[j];
            bool cand = ((f >= wl0) & (f < wh0)) | ((f >= wl1) & (f < wh1)) |
                        ((f >= wl2) & (f < wh2));
            if (cand) {
                int p = atomicAdd(&s_cnt, 1);
                if (p < CAP) list[p] = f;
            }
        }
    }
    if (tid == 0) {                      // tail
        for (int t = nfull << 2; t < n; ++t) {
            float f = xrow[t];
            bool cand = ((f >= wl0) & (f < wh0)) | ((f >= wl1) & (f < wh1)) |
                        ((f >= wl2) & (f < wh2));
            if (cand) {
                int p = atomicAdd(&s_cnt, 1);
                if (p < CAP) list[p] = f;
            }
        }
    }
    __syncthreads();

    const int cnt = min(s_cnt, CAP);
    const int ovf = (s_cnt > CAP);

    // ---- selection: warp j resolves target j ----
    if (warp < 6) {
        const int B = s_bin[warp];
        const int mexp = s_m[warp];
        const int krem = s_krem[warp];
        // interior gate: bin +-1 must be real bins (window covers B fully)
        bool need_fb = ovf || (B < 1) || (B > NBINR - 2) || (mexp > BINBUF) ||
                       (krem < 0) || (krem >= mexp);

        if (!need_fb) {
            // collect exact members of bin B from the candidate list
            const float blov = binlo_val(B), bhiv = binlo_val(B + 1);
            for (int i = lane; i < cnt; i += 32) {
                float f = list[i];
                if (f >= blov && f < bhiv) {
                    int p = atomicAdd(&bcnt[warp], 1);
                    if (p < BINBUF) binbuf[warp * BINBUF + p] = f2k(f);
                }
            }
            __syncwarp();
            if (bcnt[warp] != mexp) need_fb = true;   // verification gate
        }

        if (!need_fb) {
            // exact stable-rank among mexp (<=64) keys; uniform trips
            const unsigned* L = binbuf + warp * BINBUF;
            for (int base = 0; base < mexp; base += 32) {
                int idx = base + lane;
                unsigned e = (idx < mexp) ? L[idx] : 0xFFFFFFFFu;
                int cl = 0, ce = 0;
                for (int t = 0; t < mexp; ++t) {
                    unsigned o = L[t];              // broadcast read
                    cl += (o < e);
                    ce += (o == e && t < idx);
                }
                if (idx < mexp && cl + ce == krem) s_keyout[warp] = e;
            }
        } else {
            // exact fallback: 32-step key bisection over the full global row
            const int kglob = s_k[warp];
            unsigned prefix = 0u;
            for (int bit = 31; bit >= 0; --bit) {
                unsigned cand2 = prefix | (1u << bit);
                unsigned cc = 0;
                for (int i2 = lane; i2 < T_DIM; i2 += 32)
                    if (i2 < n) cc += (f2k(xrow[i2]) < cand2) ? 1u : 0u;
#pragma unroll
                for (int o = 16; o; o >>= 1) cc += __shfl_down_sync(FULL, cc, o);
                cc = __shfl_sync(FULL, cc, 0);
                if (cc <= (unsigned)kglob) prefix = cand2;
            }
            if (lane == 0) s_keyout[warp] = prefix;
        }
    }
    __syncthreads();

    // ---- quantile interpolation + writeback ----
    if (tid < 3) {
        float vlo = k2f(s_keyout[2 * tid]);
        float vhi = k2f(s_keyout[2 * tid + 1]);
        out[b * (5 * C_DIM) + (2 + tid) * C_DIM + c] = vlo + s_w[tid] * (vhi - vlo);
    }
}

extern "C" void kernel_launch(void* const* d_in, const int* in_sizes, int n_in,
                              void* d_out, int out_size) {
    const float* x;
    const int* lengths;
    if (in_sizes[0] == B_DIM) {
        lengths = (const int*)d_in[0];
        x = (const float*)d_in[1];
    } else {
        x = (const float*)d_in[0];
        lengths = (const int*)d_in[1];
    }
    float* out = (float*)d_out;

    // 4 KB hist + 4 KB list = 8 KB dynamic -> 8 CTAs/SM
    size_t smem = (size_t)(NBINP + CAP) * sizeof(unsigned);
    cudaFuncSetAttribute(statpool_kernel,
                         cudaFuncAttributeMaxDynamicSharedMemorySize, (int)smem);
    statpool_kernel<<<B_DIM * C_DIM, NTHREADS, smem>>>(x, lengths, out);
}